// round 17
// baseline (speedup 1.0000x reference)
#include <cuda_runtime.h>
#include <cuda_fp16.h>
#include <math.h>
#include <float.h>
#include <stdint.h>

#define BATCH 4
#define SEQ   2048
#define DM    1024
#define ROWS  (BATCH * SEQ)   // 8192

#define BM 128
#define BN 128
#define BK 32
#define LDH 40
#define THREADS 128
#define STAGES 4
#define MAT_BYTES (128 * LDH * 2)            // 10240
#define STG_BYTES (2 * MAT_BYTES)            // 20480
#define SMEM_BYTES (STAGES * STG_BYTES)      // 81920
#define NCTA 296                             // 2 CTAs x 148 SMs (all co-resident)

// Scratch (allocation-free rule: __device__ globals)
__device__ __half g_xh[(size_t)ROWS * DM];
__device__ __half g_wqh[(size_t)DM * DM];
__device__ __half g_wkh[(size_t)DM * DM];
__device__ __half g_wvh[(size_t)DM * DM];
__device__ __half g_qh[(size_t)ROWS * DM];
__device__ __half g_kh[(size_t)ROWS * DM];
__device__ __half g_vt[(size_t)BATCH * DM * SEQ];
__device__ float  g_s [(size_t)BATCH * SEQ * SEQ];
__device__ __half g_p [(size_t)BATCH * SEQ * SEQ];

// Device-wide barrier state (monotonic generation; replay-safe).
__device__ unsigned g_cnt = 0;
__device__ unsigned g_gen = 0;

__device__ __forceinline__ void mma16(float c[4], const unsigned a[4], const unsigned b[2]) {
    asm volatile(
        "mma.sync.aligned.m16n8k16.row.col.f32.f16.f16.f32 "
        "{%0,%1,%2,%3},{%4,%5,%6,%7},{%8,%9},{%0,%1,%2,%3};"
        : "+f"(c[0]), "+f"(c[1]), "+f"(c[2]), "+f"(c[3])
        : "r"(a[0]), "r"(a[1]), "r"(a[2]), "r"(a[3]), "r"(b[0]), "r"(b[1]));
}
__device__ __forceinline__ void ldsm_x4(unsigned r[4], unsigned addr) {
    asm volatile("ldmatrix.sync.aligned.m8n8.x4.shared.b16 {%0,%1,%2,%3}, [%4];"
        : "=r"(r[0]), "=r"(r[1]), "=r"(r[2]), "=r"(r[3]) : "r"(addr));
}
__device__ __forceinline__ void cp16(unsigned smem_u32, const void* gptr) {
    asm volatile("cp.async.cg.shared.global [%0], [%1], 16;\n" :: "r"(smem_u32), "l"(gptr));
}
__device__ __forceinline__ void cp_commit() { asm volatile("cp.async.commit_group;\n"); }
template<int N>
__device__ __forceinline__ void cp_wait() { asm volatile("cp.async.wait_group %0;\n" :: "n"(N)); }

// Grid-wide barrier: i-th barrier of this launch (i = 1, 2, ...).
__device__ __forceinline__ void gbar(unsigned entryGen, int i) {
    __syncthreads();
    if (threadIdx.x == 0) {
        __threadfence();
        unsigned old = atomicAdd(&g_cnt, 1u);
        if (old == NCTA - 1) {
            atomicExch(&g_cnt, 0u);
            __threadfence();
            atomicExch(&g_gen, entryGen + (unsigned)i);
        } else {
            while (*(volatile unsigned*)&g_gen < entryGen + (unsigned)i)
                __nanosleep(64);
        }
    }
    __syncthreads();
}

#define NX8 (ROWS * DM / 8)   // 1048576
#define NW8 (DM * DM / 8)     // 131072

// ---------------------------------------------------------------------------
// GEMM tile body (R12-proven). MODE 0: proj half out; MODE 3: Vt transposed;
// MODE 1: scores fp32/scale; MODE 2: PV fp32, kEnd = row0+BM.
// ---------------------------------------------------------------------------
template<int MODE>
__device__ void gemm_tile(const __half* __restrict__ A, const __half* __restrict__ B,
                          const float* __restrict__ bias, void* __restrict__ Cg,
                          int row0, int col0, __half* smem_h)
{
    const int ldA = (MODE == 2) ? SEQ : DM;
    const int ldB = (MODE == 2) ? SEQ : DM;
    const int kEnd  = (MODE == 2) ? (row0 + BM) : DM;
    const int nIter = kEnd / BK;

    const unsigned smem_base = (unsigned)__cvta_generic_to_shared(smem_h);
    const int tid = threadIdx.x;

    auto issue = [&](int it) {
        const int k0 = it * BK;
        const unsigned sa = smem_base + (it % STAGES) * STG_BYTES;
        const unsigned sb = sa + MAT_BYTES;
        #pragma unroll
        for (int t = 0; t < 4; ++t) {
            int cid = tid + t * THREADS;
            int r = cid >> 2, c8 = (cid & 3) * 8;
            cp16(sa + (r * LDH + c8) * 2, A + (size_t)(row0 + r) * ldA + k0 + c8);
        }
        #pragma unroll
        for (int t = 0; t < 4; ++t) {
            int cid = tid + t * THREADS;
            int r = cid >> 2, c8 = (cid & 3) * 8;
            cp16(sb + (r * LDH + c8) * 2, B + (size_t)(col0 + r) * ldB + k0 + c8);
        }
    };

    const int lane = tid & 31;
    const int wid = tid >> 5;
    const int wm = (wid >> 1) * 64;
    const int wn = (wid & 1) * 64;
    const int lq = lane >> 2, lr = lane & 3;

    const int lr8 = lane & 7;
    const unsigned aoff = (unsigned)(((wm + lr8 + ((lane >> 3) & 1) * 8) * LDH
                                      + ((lane >> 4) & 1) * 8) * 2);
    const unsigned boff = (unsigned)(((wn + lr8 + ((lane >> 4) & 1) * 8) * LDH
                                      + ((lane >> 3) & 1) * 8) * 2);

    float acc[4][8][4] = {};

    #pragma unroll
    for (int s = 0; s < STAGES - 1; ++s) {
        if (s < nIter) issue(s);
        cp_commit();
    }

    for (int it = 0; it < nIter; ++it) {
        cp_wait<STAGES - 2>();
        __syncthreads();

        if (it + STAGES - 1 < nIter) issue(it + STAGES - 1);
        cp_commit();

        const unsigned sA = smem_base + (it % STAGES) * STG_BYTES;
        const unsigned sB = sA + MAT_BYTES;

        #pragma unroll
        for (int ks = 0; ks < 2; ++ks) {
            unsigned af[4][4], bf[8][2];
            #pragma unroll
            for (int i = 0; i < 4; ++i)
                ldsm_x4(af[i], sA + aoff + (unsigned)((i * 16 * LDH + ks * 16) * 2));
            #pragma unroll
            for (int j2 = 0; j2 < 4; ++j2) {
                unsigned bb[4];
                ldsm_x4(bb, sB + boff + (unsigned)((j2 * 16 * LDH + ks * 16) * 2));
                bf[2 * j2][0] = bb[0]; bf[2 * j2][1] = bb[1];
                bf[2 * j2 + 1][0] = bb[2]; bf[2 * j2 + 1][1] = bb[3];
            }
            #pragma unroll
            for (int i = 0; i < 4; ++i)
                #pragma unroll
                for (int j = 0; j < 8; ++j)
                    mma16(acc[i][j], af[i], bf[j]);
        }
    }
    __syncthreads();   // smem reuse (epilogue staging / next job)

    if (MODE == 0) {
        __half* C = (__half*)Cg;
        #pragma unroll
        for (int i = 0; i < 4; ++i) {
            const int r = row0 + wm + i * 16 + lq;
            #pragma unroll
            for (int j = 0; j < 8; ++j) {
                const int c = col0 + wn + j * 8 + 2 * lr;
                const float b0 = bias[c], b1 = bias[c + 1];
                *(__half2*)&C[(size_t)r * DM + c] =
                    __float22half2_rn(make_float2(acc[i][j][0] + b0, acc[i][j][1] + b1));
                *(__half2*)&C[(size_t)(r + 8) * DM + c] =
                    __float22half2_rn(make_float2(acc[i][j][2] + b0, acc[i][j][3] + b1));
            }
        }
    } else if (MODE == 1) {
        float* C = (float*)Cg;
        const float scale = 1.0f / 32.0f;
        #pragma unroll
        for (int i = 0; i < 4; ++i) {
            const int r = row0 + wm + i * 16 + lq;
            #pragma unroll
            for (int j = 0; j < 8; ++j) {
                const int c = col0 + wn + j * 8 + 2 * lr;
                *(float2*)&C[(size_t)r * SEQ + c] =
                    make_float2(acc[i][j][0] * scale, acc[i][j][1] * scale);
                *(float2*)&C[(size_t)(r + 8) * SEQ + c] =
                    make_float2(acc[i][j][2] * scale, acc[i][j][3] * scale);
            }
        }
    } else if (MODE == 2) {
        float* C = (float*)Cg;
        #pragma unroll
        for (int i = 0; i < 4; ++i) {
            const int r = row0 + wm + i * 16 + lq;
            #pragma unroll
            for (int j = 0; j < 8; ++j) {
                const int c = col0 + wn + j * 8 + 2 * lr;
                *(float2*)&C[(size_t)r * DM + c] = make_float2(acc[i][j][0], acc[i][j][1]);
                *(float2*)&C[(size_t)(r + 8) * DM + c] = make_float2(acc[i][j][2], acc[i][j][3]);
            }
        }
    } else {
        // MODE 3: transposed Vt store via per-warp smem staging (64n x 64m, pad 72)
        __half* ts = smem_h + (size_t)wid * 64 * 72;
        #pragma unroll
        for (int i = 0; i < 4; ++i) {
            const int ml = i * 16 + lq;
            #pragma unroll
            for (int j = 0; j < 8; ++j) {
                const int nl = j * 8 + 2 * lr;
                const int c = col0 + wn + nl;
                const float b0 = bias[c], b1 = bias[c + 1];
                ts[nl * 72 + ml]           = __float2half_rn(acc[i][j][0] + b0);
                ts[(nl + 1) * 72 + ml]     = __float2half_rn(acc[i][j][1] + b1);
                ts[nl * 72 + ml + 8]       = __float2half_rn(acc[i][j][2] + b0);
                ts[(nl + 1) * 72 + ml + 8] = __float2half_rn(acc[i][j][3] + b1);
            }
        }
        __syncwarp();
        __half* vtb = (__half*)Cg + (size_t)(row0 >> 11) * DM * SEQ;
        const int s0 = (row0 & (SEQ - 1)) + wm;
        #pragma unroll
        for (int nr2 = 0; nr2 < 2; ++nr2) {
            const int nr = lane + nr2 * 32;
            const int n = col0 + wn + nr;
            #pragma unroll
            for (int i8 = 0; i8 < 8; ++i8) {
                uint4 v = *(uint4*)&ts[nr * 72 + i8 * 8];
                *(uint4*)&vtb[(size_t)n * SEQ + s0 + i8 * 8] = v;
            }
        }
        __syncthreads();
    }
}

// ---------------------------------------------------------------------------
// 128-thread registerized softmax for one row (R12 math, rescaled to 128 thr).
// ---------------------------------------------------------------------------
__device__ void softmax_row(const float* __restrict__ row, __half* __restrict__ prow,
                            int qi, float* red)
{
    const int L = qi + 1;
    const int L4 = L >> 2;                 // <= 512 float4; 4 per thread max
    const int tid = threadIdx.x;
    const int wid = tid >> 5, lane = tid & 31;

    float4 v[4];
    bool hv[4];
    #pragma unroll
    for (int k = 0; k < 4; ++k) {
        hv[k] = (tid + k * 128) < L4;
        if (hv[k]) v[k] = ((const float4*)row)[tid + k * 128];
    }
    const int ti = L4 * 4 + tid;
    const bool ht = ti < L;
    float vt = ht ? row[ti] : 0.0f;

    float m = -FLT_MAX;
    #pragma unroll
    for (int k = 0; k < 4; ++k)
        if (hv[k]) m = fmaxf(m, fmaxf(fmaxf(v[k].x, v[k].y), fmaxf(v[k].z, v[k].w)));
    if (ht) m = fmaxf(m, vt);
    #pragma unroll
    for (int o = 16; o; o >>= 1) m = fmaxf(m, __shfl_xor_sync(0xffffffffu, m, o));
    if (lane == 0) red[wid] = m;
    __syncthreads();
    float M = fmaxf(fmaxf(red[0], red[1]), fmaxf(red[2], red[3]));
    __syncthreads();

    const float c2 = 1.4426950408889634f;
    float s = 0.0f;
    float4 e[4];
    float et = 0.0f;
    #pragma unroll
    for (int k = 0; k < 4; ++k) {
        if (hv[k]) {
            e[k].x = exp2f((v[k].x - M) * c2); e[k].y = exp2f((v[k].y - M) * c2);
            e[k].z = exp2f((v[k].z - M) * c2); e[k].w = exp2f((v[k].w - M) * c2);
            s += e[k].x + e[k].y + e[k].z + e[k].w;
        }
    }
    if (ht) { et = exp2f((vt - M) * c2); s += et; }
    #pragma unroll
    for (int o = 16; o; o >>= 1) s += __shfl_xor_sync(0xffffffffu, s, o);
    if (lane == 0) red[wid] = s;
    __syncthreads();
    const float inv = 1.0f / (red[0] + red[1] + red[2] + red[3]);
    __syncthreads();

    #pragma unroll
    for (int k = 0; k < 4; ++k) {
        if (hv[k]) {
            __half2 a = __float22half2_rn(make_float2(e[k].x * inv, e[k].y * inv));
            __half2 b = __float22half2_rn(make_float2(e[k].z * inv, e[k].w * inv));
            uint2 o; o.x = *(unsigned*)&a; o.y = *(unsigned*)&b;
            ((uint2*)prow)[tid + k * 128] = o;
        }
    }
    if (ht) prow[ti] = __float2half_rn(et * inv);

    const int zEnd = (qi & ~127) + 128;
    for (int j = L + tid; j < zEnd; j += 128) prow[j] = __float2half_rn(0.0f);
}

// ---------------------------------------------------------------------------
// Persistent mega-kernel: all 5 phases, grid-wide barriers between them.
// ---------------------------------------------------------------------------
__global__ __launch_bounds__(THREADS, 2) void mega(
    const float* __restrict__ x,
    const float* __restrict__ Wq, const float* __restrict__ bq,
    const float* __restrict__ Wk, const float* __restrict__ bk,
    const float* __restrict__ Wv, const float* __restrict__ bv,
    float* __restrict__ out)
{
    extern __shared__ __align__(16) __half smem_h[];
    __shared__ float red[4];

    const int cta = blockIdx.x;
    const int tid = threadIdx.x;

    unsigned entryGen = 0;
    if (tid == 0) entryGen = *(volatile unsigned*)&g_gen;

    // ---- Phase 0: fp32 -> fp16 conversion (grid-stride over 8-elem chunks)
    {
        const int nAll = NX8 + 3 * NW8;
        for (int i = cta * THREADS + tid; i < nAll; i += NCTA * THREADS) {
            const float* in;
            __half* o;
            int j;
            if (i < NX8)                { in = x;  o = g_xh;  j = i; }
            else if (i < NX8 + NW8)     { in = Wq; o = g_wqh; j = i - NX8; }
            else if (i < NX8 + 2 * NW8) { in = Wk; o = g_wkh; j = i - NX8 - NW8; }
            else                        { in = Wv; o = g_wvh; j = i - NX8 - 2 * NW8; }
            float4 a = ((const float4*)in)[2 * j];
            float4 b = ((const float4*)in)[2 * j + 1];
            __half2 h0 = __float22half2_rn(make_float2(a.x, a.y));
            __half2 h1 = __float22half2_rn(make_float2(a.z, a.w));
            __half2 h2 = __float22half2_rn(make_float2(b.x, b.y));
            __half2 h3 = __float22half2_rn(make_float2(b.z, b.w));
            uint4 ov;
            ov.x = *(unsigned*)&h0; ov.y = *(unsigned*)&h1;
            ov.z = *(unsigned*)&h2; ov.w = *(unsigned*)&h3;
            ((uint4*)o)[j] = ov;
        }
    }
    gbar(entryGen, 1);

    // ---- Phase 1: QKV projections (1536 tile jobs; z = job>>9)
    for (int job = cta; job < 1536; job += NCTA) {
        const int z = job >> 9;
        const int r = job & 511;
        const int row0 = (r >> 3) * BM;
        const int col0 = (r & 7) * BN;
        if (z == 0)      gemm_tile<0>(g_xh, g_wqh, bq, g_qh, row0, col0, smem_h);
        else if (z == 1) gemm_tile<0>(g_xh, g_wkh, bk, g_kh, row0, col0, smem_h);
        else             gemm_tile<3>(g_xh, g_wvh, bv, g_vt, row0, col0, smem_h);
    }
    gbar(entryGen, 2);

    // ---- Phase 2: causal scores (544 packed triangular jobs)
    for (int job = cta; job < 136 * BATCH; job += NCTA) {
        const int b = job / 136;
        const int t = job % 136;
        int y = (int)((sqrtf(8.0f * (float)t + 1.0f) - 1.0f) * 0.5f);
        while ((y + 1) * (y + 2) / 2 <= t) ++y;
        while (y * (y + 1) / 2 > t) --y;
        const int row0 = y * BM;
        const int col0 = (t - y * (y + 1) / 2) * BN;
        const __half* qb = g_qh + (size_t)b * SEQ * DM;
        const __half* kb = g_kh + (size_t)b * SEQ * DM;
        float* sb = g_s + (size_t)b * SEQ * SEQ;
        gemm_tile<1>(qb, kb, nullptr, sb, row0, col0, smem_h);
    }
    gbar(entryGen, 3);

    // ---- Phase 3: softmax (8192 rows)
    for (int rrow = cta; rrow < ROWS; rrow += NCTA) {
        const int qi = rrow & (SEQ - 1);
        const float* srow = g_s + (size_t)rrow * SEQ;
        __half* prow = g_p + (size_t)rrow * SEQ;
        softmax_row(srow, prow, qi, red);
        __syncthreads();
    }
    gbar(entryGen, 4);

    // ---- Phase 4: PV (512 jobs, longest rows first)
    for (int job = cta; job < 512; job += NCTA) {
        const int b = job >> 7;
        const int j2 = job & 127;
        const int row0 = (15 - (j2 >> 3)) * BM;   // longest-first
        const int col0 = (j2 & 7) * BN;
        const __half* pb = g_p + (size_t)b * SEQ * SEQ;
        const __half* vb = g_vt + (size_t)b * DM * SEQ;
        float* ob = out + (size_t)b * SEQ * DM;
        gemm_tile<2>(pb, vb, nullptr, ob, row0, col0, smem_h);
    }
}

// ---------------------------------------------------------------------------
extern "C" void kernel_launch(void* const* d_in, const int* in_sizes, int n_in,
                              void* d_out, int out_size)
{
    (void)in_sizes; (void)n_in; (void)out_size;
    const float* x  = (const float*)d_in[0];
    const float* Wq = (const float*)d_in[1];
    const float* bq = (const float*)d_in[2];
    const float* Wk = (const float*)d_in[3];
    const float* bk = (const float*)d_in[4];
    const float* Wv = (const float*)d_in[5];
    const float* bv = (const float*)d_in[6];
    float* out = (float*)d_out;

    cudaFuncSetAttribute(mega, cudaFuncAttributeMaxDynamicSharedMemorySize, SMEM_BYTES);
    mega<<<NCTA, THREADS, SMEM_BYTES>>>(x, Wq, bq, Wk, bk, Wv, bv, out);
}